// round 4
// baseline (speedup 1.0000x reference)
#include <cuda_runtime.h>
#include <math.h>

#define NB    4
#define NPTS  8192
#define KNN   32
#define NE    (NB*NPTS*KNN)      /* 1048576 edges */
#define EPB   (NPTS*KNN)         /* 262144 edges per batch */
#define BC    256
#define CNTF  ((float)EPB)
#define EPSV  1e-5f
#define SLOPE 0.1f

// SoA by channel-quad: plane c4 holds float4 of channels [4c4,4c4+4) per edge
__device__ float4 g_Y[(size_t)16 * NE];
__device__ __align__(16) float g_sum[BC], g_sumsq[BC], g_s[BC], g_t[BC];

// ---------------------------------------------------------------- f32x2 ops
__device__ __forceinline__ unsigned long long fma2(unsigned long long a,
                                                   unsigned long long b,
                                                   unsigned long long c) {
    unsigned long long d;
    asm("fma.rn.f32x2 %0, %1, %2, %3;" : "=l"(d) : "l"(a), "l"(b), "l"(c));
    return d;
}
__device__ __forceinline__ unsigned long long dup2(float x) {
    unsigned long long d;
    asm("mov.b64 %0, {%1, %1};" : "=l"(d) : "f"(x));
    return d;
}
__device__ __forceinline__ float2 unp2(unsigned long long v) {
    float2 r;
    asm("mov.b64 {%0, %1}, %2;" : "=f"(r.x), "=f"(r.y) : "l"(v));
    return r;
}

// ---------------------------------------------------------------- zero stats
__global__ void k_zero() {
    int i = threadIdx.x;
    g_sum[i] = 0.f; g_sumsq[i] = 0.f;
}

// ---- shared epilogue: store acc planes + fused per-channel stats reduction
__device__ __forceinline__ void epilogue(unsigned long long acc[4][8],
                                         size_t e0, int og, int b) {
    #pragma unroll
    for (int ed = 0; ed < 4; ed++) {
        #pragma unroll
        for (int p = 0; p < 4; p++) {
            ulonglong2 v; v.x = acc[ed][2*p]; v.y = acc[ed][2*p+1];
            *((ulonglong2*)&g_Y[(size_t)(og*4 + p)*NE + e0 + ed*64]) = v;
        }
    }
    float s[16], q[16];
    #pragma unroll
    for (int j = 0; j < 8; j++) {
        float2 a0 = unp2(acc[0][j]), a1 = unp2(acc[1][j]);
        float2 a2 = unp2(acc[2][j]), a3 = unp2(acc[3][j]);
        s[2*j]   = (a0.x + a1.x) + (a2.x + a3.x);
        s[2*j+1] = (a0.y + a1.y) + (a2.y + a3.y);
        q[2*j]   = fmaf(a0.x,a0.x, fmaf(a1.x,a1.x, fmaf(a2.x,a2.x, a3.x*a3.x)));
        q[2*j+1] = fmaf(a0.y,a0.y, fmaf(a1.y,a1.y, fmaf(a2.y,a2.y, a3.y*a3.y)));
    }
    #pragma unroll
    for (int off = 16; off; off >>= 1) {
        #pragma unroll
        for (int i = 0; i < 16; i++) {
            s[i] += __shfl_down_sync(0xffffffffu, s[i], off);
            q[i] += __shfl_down_sync(0xffffffffu, q[i], off);
        }
    }
    if ((threadIdx.x & 31) == 0) {
        int cb = b*64 + og*16;
        #pragma unroll
        for (int i = 0; i < 16; i++) {
            atomicAdd(&g_sum[cb+i], s[i]);
            atomicAdd(&g_sumsq[cb+i], q[i]);
        }
    }
}

// ------------------------------------------- stage 1: gather + concat + GEMM1
__global__ void __launch_bounds__(256) k_stage1(
    const float* __restrict__ signal, const int* __restrict__ edges,
    const float* __restrict__ efeat,  const float* __restrict__ W1)
{
    __shared__ __align__(16) float sW[35*64];   // sW[c*64+o] = W1[o][c]
    for (int i = threadIdx.x; i < 35*64; i += 256) {
        int o = i / 35, c = i - o*35;
        sW[c*64 + o] = W1[i];
    }
    __syncthreads();

    int og = threadIdx.x >> 6, ei = threadIdx.x & 63;
    int b  = blockIdx.x >> 10;
    size_t e0 = (size_t)blockIdx.x * 256 + ei;

    const float4* rp[4];
    #pragma unroll
    for (int ed = 0; ed < 4; ed++) {
        int idx = edges[e0 + ed*64];
        rp[ed] = (const float4*)signal + (size_t)idx * 8;
    }

    unsigned long long acc[4][8];
    #pragma unroll
    for (int ed = 0; ed < 4; ed++)
        #pragma unroll
        for (int j = 0; j < 8; j++) acc[ed][j] = 0ull;

    #pragma unroll 2
    for (int c4 = 0; c4 < 8; c4++) {
        float xq[4][4];
        #pragma unroll
        for (int ed = 0; ed < 4; ed++) {
            float4 v = rp[ed][c4];
            xq[ed][0]=v.x; xq[ed][1]=v.y; xq[ed][2]=v.z; xq[ed][3]=v.w;
        }
        #pragma unroll
        for (int cc = 0; cc < 4; cc++) {
            const ulonglong2* wp = (const ulonglong2*)(sW + (c4*4+cc)*64 + og*16);
            ulonglong2 w0=wp[0], w1=wp[1], w2=wp[2], w3=wp[3];
            #pragma unroll
            for (int ed = 0; ed < 4; ed++) {
                unsigned long long xd = dup2(xq[ed][cc]);
                acc[ed][0]=fma2(w0.x,xd,acc[ed][0]); acc[ed][1]=fma2(w0.y,xd,acc[ed][1]);
                acc[ed][2]=fma2(w1.x,xd,acc[ed][2]); acc[ed][3]=fma2(w1.y,xd,acc[ed][3]);
                acc[ed][4]=fma2(w2.x,xd,acc[ed][4]); acc[ed][5]=fma2(w2.y,xd,acc[ed][5]);
                acc[ed][6]=fma2(w3.x,xd,acc[ed][6]); acc[ed][7]=fma2(w3.y,xd,acc[ed][7]);
            }
        }
    }
    // edge-feature channels 32..34
    float ef[4][3];
    #pragma unroll
    for (int ed = 0; ed < 4; ed++) {
        size_t base = 3*(e0 + ed*64);
        ef[ed][0]=efeat[base]; ef[ed][1]=efeat[base+1]; ef[ed][2]=efeat[base+2];
    }
    #pragma unroll
    for (int cc = 0; cc < 3; cc++) {
        const ulonglong2* wp = (const ulonglong2*)(sW + (32+cc)*64 + og*16);
        ulonglong2 w0=wp[0], w1=wp[1], w2=wp[2], w3=wp[3];
        #pragma unroll
        for (int ed = 0; ed < 4; ed++) {
            unsigned long long xd = dup2(ef[ed][cc]);
            acc[ed][0]=fma2(w0.x,xd,acc[ed][0]); acc[ed][1]=fma2(w0.y,xd,acc[ed][1]);
            acc[ed][2]=fma2(w1.x,xd,acc[ed][2]); acc[ed][3]=fma2(w1.y,xd,acc[ed][3]);
            acc[ed][4]=fma2(w2.x,xd,acc[ed][4]); acc[ed][5]=fma2(w2.y,xd,acc[ed][5]);
            acc[ed][6]=fma2(w3.x,xd,acc[ed][6]); acc[ed][7]=fma2(w3.y,xd,acc[ed][7]);
        }
    }
    epilogue(acc, e0, og, b);
}

// ------------------------------------- stats -> (scale, shift), reset accum
__global__ void k_finalize(const float* __restrict__ gam, const float* __restrict__ bet) {
    int i = threadIdx.x;          // 256 = (b,c)
    float mean = g_sum[i]   * (1.f/CNTF);
    float var  = g_sumsq[i] * (1.f/CNTF) - mean*mean;
    float sc   = gam[i & 63] * rsqrtf(var + EPSV);
    g_s[i] = sc;
    g_t[i] = bet[i & 63] - mean * sc;
    g_sum[i] = 0.f; g_sumsq[i] = 0.f;
}

// --------------------- stages 2/3: norm + leaky + 64x64 GEMM (in-place on Y)
__global__ void __launch_bounds__(256) k_stage(const float* __restrict__ W) {
    __shared__ __align__(16) float sW[64*64];   // sW[c*64+o] = W[o][c]
    __shared__ float sS[64], sT[64];
    int b = blockIdx.x >> 10;
    for (int i = threadIdx.x; i < 4096; i += 256) {
        int o = i >> 6, c = i & 63;
        sW[c*64 + o] = W[i];
    }
    if (threadIdx.x < 64) {
        sS[threadIdx.x] = g_s[b*64 + threadIdx.x];
        sT[threadIdx.x] = g_t[b*64 + threadIdx.x];
    }
    __syncthreads();

    int og = threadIdx.x >> 6, ei = threadIdx.x & 63;
    size_t e0 = (size_t)blockIdx.x * 256 + ei;

    unsigned long long acc[4][8];
    #pragma unroll
    for (int ed = 0; ed < 4; ed++)
        #pragma unroll
        for (int j = 0; j < 8; j++) acc[ed][j] = 0ull;

    #pragma unroll 2
    for (int c4 = 0; c4 < 16; c4++) {
        float s0=sS[4*c4+0], s1=sS[4*c4+1], s2=sS[4*c4+2], s3=sS[4*c4+3];
        float t0=sT[4*c4+0], t1=sT[4*c4+1], t2=sT[4*c4+2], t3=sT[4*c4+3];
        float xn[4][4];
        #pragma unroll
        for (int ed = 0; ed < 4; ed++) {
            float4 v = g_Y[(size_t)c4*NE + e0 + ed*64];
            float y;
            y = fmaf(v.x, s0, t0); xn[ed][0] = (y>=0.f)?y:SLOPE*y;
            y = fmaf(v.y, s1, t1); xn[ed][1] = (y>=0.f)?y:SLOPE*y;
            y = fmaf(v.z, s2, t2); xn[ed][2] = (y>=0.f)?y:SLOPE*y;
            y = fmaf(v.w, s3, t3); xn[ed][3] = (y>=0.f)?y:SLOPE*y;
        }
        #pragma unroll
        for (int cc = 0; cc < 4; cc++) {
            const ulonglong2* wp = (const ulonglong2*)(sW + (c4*4+cc)*64 + og*16);
            ulonglong2 w0=wp[0], w1=wp[1], w2=wp[2], w3=wp[3];
            #pragma unroll
            for (int ed = 0; ed < 4; ed++) {
                unsigned long long xd = dup2(xn[ed][cc]);
                acc[ed][0]=fma2(w0.x,xd,acc[ed][0]); acc[ed][1]=fma2(w0.y,xd,acc[ed][1]);
                acc[ed][2]=fma2(w1.x,xd,acc[ed][2]); acc[ed][3]=fma2(w1.y,xd,acc[ed][3]);
                acc[ed][4]=fma2(w2.x,xd,acc[ed][4]); acc[ed][5]=fma2(w2.y,xd,acc[ed][5]);
                acc[ed][6]=fma2(w3.x,xd,acc[ed][6]); acc[ed][7]=fma2(w3.y,xd,acc[ed][7]);
            }
        }
    }
    __syncthreads();   // all reads of this block's edges done before in-place stores
    epilogue(acc, e0, og, (int)(blockIdx.x >> 10));
}

// -------- final: norm3 + leaky + max over K (warp per (point, c4)), coalesced
__global__ void __launch_bounds__(256) k_out(float* __restrict__ out) {
    int w    = blockIdx.x * 8 + (threadIdx.x >> 5);   // warp id: (r, c4)
    int lane = threadIdx.x & 31;
    int c4 = w & 15;
    int r  = w >> 4;                 // b*N + n
    int b  = r >> 13;
    float4 sc = ((const float4*)g_s)[b*16 + c4];
    float4 tt = ((const float4*)g_t)[b*16 + c4];
    float4 v = g_Y[(size_t)c4*NE + (size_t)r*KNN + lane];
    float4 y;
    y.x = fmaf(v.x, sc.x, tt.x); y.x = (y.x>=0.f)?y.x:SLOPE*y.x;
    y.y = fmaf(v.y, sc.y, tt.y); y.y = (y.y>=0.f)?y.y:SLOPE*y.y;
    y.z = fmaf(v.z, sc.z, tt.z); y.z = (y.z>=0.f)?y.z:SLOPE*y.z;
    y.w = fmaf(v.w, sc.w, tt.w); y.w = (y.w>=0.f)?y.w:SLOPE*y.w;
    #pragma unroll
    for (int off = 16; off; off >>= 1) {
        y.x = fmaxf(y.x, __shfl_xor_sync(0xffffffffu, y.x, off));
        y.y = fmaxf(y.y, __shfl_xor_sync(0xffffffffu, y.y, off));
        y.z = fmaxf(y.z, __shfl_xor_sync(0xffffffffu, y.z, off));
        y.w = fmaxf(y.w, __shfl_xor_sync(0xffffffffu, y.w, off));
    }
    if (lane == 0) ((float4*)out)[(size_t)r*16 + c4] = y;
}

// ---------------------------------------------------------------------------
extern "C" void kernel_launch(void* const* d_in, const int* in_sizes, int n_in,
                              void* d_out, int out_size)
{
    const float* signal = (const float*)d_in[0];
    const int*   edges  = (const int*)d_in[1];
    const float* efeat  = (const float*)d_in[2];
    // d_in[3] = k (constant 32, baked in)
    const float* W1 = (const float*)d_in[4];
    const float* g1 = (const float*)d_in[5];
    const float* b1 = (const float*)d_in[6];
    const float* W2 = (const float*)d_in[7];
    const float* g2 = (const float*)d_in[8];
    const float* b2 = (const float*)d_in[9];
    const float* W3 = (const float*)d_in[10];
    const float* g3 = (const float*)d_in[11];
    const float* b3 = (const float*)d_in[12];
    float* out = (float*)d_out;

    k_zero<<<1, 256>>>();
    k_stage1<<<NE/256, 256>>>(signal, edges, efeat, W1);
    k_finalize<<<1, 256>>>(g1, b1);
    k_stage<<<NE/256, 256>>>(W2);
    k_finalize<<<1, 256>>>(g2, b2);
    k_stage<<<NE/256, 256>>>(W3);
    k_finalize<<<1, 256>>>(g3, b3);
    k_out<<<(NB*NPTS*16)/8, 256>>>(out);
}

// round 5
// speedup vs baseline: 1.9555x; 1.9555x over previous
#include <cuda_runtime.h>
#include <math.h>

#define NB    4
#define NPTS  8192
#define KNN   32
#define NE    (NB*NPTS*KNN)      /* 1048576 edges */
#define EPB   (NPTS*KNN)         /* 262144 edges per batch */
#define BC    256
#define CNTF  ((float)EPB)
#define EPSV  1e-5f
#define SLOPE 0.1f

// SoA by channel-quad: plane c4 holds float4 of channels [4c4,4c4+4) per edge
__device__ float4 g_Y[(size_t)16 * NE];
__device__ __align__(16) float g_sum[BC], g_sumsq[BC], g_s[BC], g_t[BC];

// ---------------------------------------------------------------- helpers
__device__ __forceinline__ unsigned long long fma2(unsigned long long a,
                                                   unsigned long long b,
                                                   unsigned long long c) {
    unsigned long long d;
    asm("fma.rn.f32x2 %0, %1, %2, %3;" : "=l"(d) : "l"(a), "l"(b), "l"(c));
    return d;
}
__device__ __forceinline__ unsigned long long dup2(float x) {
    unsigned long long d;
    asm("mov.b64 %0, {%1, %1};" : "=l"(d) : "f"(x));
    return d;
}
__device__ __forceinline__ float2 unp2(unsigned long long v) {
    float2 r;
    asm("mov.b64 {%0, %1}, %2;" : "=f"(r.x), "=f"(r.y) : "l"(v));
    return r;
}
__device__ __forceinline__ unsigned tf32h(float x) {
    unsigned r;
    asm("cvt.rna.tf32.f32 %0, %1;" : "=r"(r) : "f"(x));
    return r;
}
__device__ __forceinline__ void mma8(float* c,
                                     unsigned a0, unsigned a1, unsigned a2, unsigned a3,
                                     unsigned b0, unsigned b1) {
    asm("mma.sync.aligned.m16n8k8.row.col.f32.tf32.tf32.f32 "
        "{%0,%1,%2,%3},{%4,%5,%6,%7},{%8,%9},{%0,%1,%2,%3};"
        : "+f"(c[0]), "+f"(c[1]), "+f"(c[2]), "+f"(c[3])
        : "r"(a0), "r"(a1), "r"(a2), "r"(a3), "r"(b0), "r"(b1));
}

// transpose-reduce: 32 values across 32 lanes; after, lane l holds total of value l
__device__ __forceinline__ void xpose_reduce(float v[32]) {
    int lane = threadIdx.x & 31;
    #pragma unroll
    for (int off = 16; off >= 1; off >>= 1) {
        bool up = (lane & off) != 0;
        #pragma unroll
        for (int j = 0; j < off; j++) {
            float send = up ? v[j] : v[j + off];
            float t = __shfl_xor_sync(0xffffffffu, send, off);
            v[j] = (up ? v[j + off] : v[j]) + t;
        }
    }
}

// ---------------------------------------------------------------- zero stats
__global__ void k_zero() {
    int i = threadIdx.x;
    g_sum[i] = 0.f; g_sumsq[i] = 0.f;
}

// ------------------------------------------- stage 1: gather + concat + GEMM1
// 128 edges/block, 2 edges/thread, fused stats
__global__ void __launch_bounds__(256) k_stage1(
    const float* __restrict__ signal, const int* __restrict__ edges,
    const float* __restrict__ efeat,  const float* __restrict__ W1)
{
    __shared__ __align__(16) float sW[35*64];   // sW[c*64+o] = W1[o][c]
    for (int i = threadIdx.x; i < 35*64; i += 256) {
        int o = i / 35, c = i - o*35;
        sW[c*64 + o] = W1[i];
    }
    __syncthreads();

    int og = threadIdx.x >> 6, ei = threadIdx.x & 63;
    int b  = blockIdx.x >> 11;
    size_t e0 = (size_t)blockIdx.x * 128 + ei;

    const float4* rp[2];
    rp[0] = (const float4*)signal + (size_t)edges[e0] * 8;
    rp[1] = (const float4*)signal + (size_t)edges[e0 + 64] * 8;

    unsigned long long acc[2][8];
    #pragma unroll
    for (int ed = 0; ed < 2; ed++)
        #pragma unroll
        for (int j = 0; j < 8; j++) acc[ed][j] = 0ull;

    #pragma unroll 2
    for (int c4 = 0; c4 < 8; c4++) {
        float4 v0 = rp[0][c4], v1 = rp[1][c4];
        float xq[2][4];
        xq[0][0]=v0.x; xq[0][1]=v0.y; xq[0][2]=v0.z; xq[0][3]=v0.w;
        xq[1][0]=v1.x; xq[1][1]=v1.y; xq[1][2]=v1.z; xq[1][3]=v1.w;
        #pragma unroll
        for (int cc = 0; cc < 4; cc++) {
            const ulonglong2* wp = (const ulonglong2*)(sW + (c4*4+cc)*64 + og*16);
            ulonglong2 w0=wp[0], w1=wp[1], w2=wp[2], w3=wp[3];
            #pragma unroll
            for (int ed = 0; ed < 2; ed++) {
                unsigned long long xd = dup2(xq[ed][cc]);
                acc[ed][0]=fma2(w0.x,xd,acc[ed][0]); acc[ed][1]=fma2(w0.y,xd,acc[ed][1]);
                acc[ed][2]=fma2(w1.x,xd,acc[ed][2]); acc[ed][3]=fma2(w1.y,xd,acc[ed][3]);
                acc[ed][4]=fma2(w2.x,xd,acc[ed][4]); acc[ed][5]=fma2(w2.y,xd,acc[ed][5]);
                acc[ed][6]=fma2(w3.x,xd,acc[ed][6]); acc[ed][7]=fma2(w3.y,xd,acc[ed][7]);
            }
        }
    }
    // edge-feature channels 32..34
    float ef[2][3];
    #pragma unroll
    for (int ed = 0; ed < 2; ed++) {
        size_t base = 3*(e0 + (size_t)ed*64);
        ef[ed][0]=efeat[base]; ef[ed][1]=efeat[base+1]; ef[ed][2]=efeat[base+2];
    }
    #pragma unroll
    for (int cc = 0; cc < 3; cc++) {
        const ulonglong2* wp = (const ulonglong2*)(sW + (32+cc)*64 + og*16);
        ulonglong2 w0=wp[0], w1=wp[1], w2=wp[2], w3=wp[3];
        #pragma unroll
        for (int ed = 0; ed < 2; ed++) {
            unsigned long long xd = dup2(ef[ed][cc]);
            acc[ed][0]=fma2(w0.x,xd,acc[ed][0]); acc[ed][1]=fma2(w0.y,xd,acc[ed][1]);
            acc[ed][2]=fma2(w1.x,xd,acc[ed][2]); acc[ed][3]=fma2(w1.y,xd,acc[ed][3]);
            acc[ed][4]=fma2(w2.x,xd,acc[ed][4]); acc[ed][5]=fma2(w2.y,xd,acc[ed][5]);
            acc[ed][6]=fma2(w3.x,xd,acc[ed][6]); acc[ed][7]=fma2(w3.y,xd,acc[ed][7]);
        }
    }
    // store (SoA planes)
    #pragma unroll
    for (int ed = 0; ed < 2; ed++) {
        #pragma unroll
        for (int p = 0; p < 4; p++) {
            ulonglong2 v; v.x = acc[ed][2*p]; v.y = acc[ed][2*p+1];
            *((ulonglong2*)&g_Y[(size_t)(og*4 + p)*NE + e0 + (size_t)ed*64]) = v;
        }
    }
    // fused stats: 16 ch sums + 16 sq over this thread's 2 edges
    float v32[32];
    #pragma unroll
    for (int j = 0; j < 8; j++) {
        float2 a0 = unp2(acc[0][j]), a1 = unp2(acc[1][j]);
        v32[2*j]      = a0.x + a1.x;
        v32[2*j+1]    = a0.y + a1.y;
        v32[16+2*j]   = fmaf(a0.x,a0.x, a1.x*a1.x);
        v32[16+2*j+1] = fmaf(a0.y,a0.y, a1.y*a1.y);
    }
    xpose_reduce(v32);
    int lane = threadIdx.x & 31;
    if (lane < 16) atomicAdd(&g_sum[b*64 + og*16 + lane], v32[0]);
    else           atomicAdd(&g_sumsq[b*64 + og*16 + lane - 16], v32[0]);
}

// ------------------------------------- stats -> (scale, shift), reset accum
__global__ void k_finalize(const float* __restrict__ gam, const float* __restrict__ bet) {
    int i = threadIdx.x;          // 256 = (b,c)
    float mean = g_sum[i]   * (1.f/CNTF);
    float var  = g_sumsq[i] * (1.f/CNTF) - mean*mean;
    float sc   = gam[i & 63] * rsqrtf(var + EPSV);
    g_s[i] = sc;
    g_t[i] = bet[i & 63] - mean * sc;
    g_sum[i] = 0.f; g_sumsq[i] = 0.f;
}

// ------- stages 2/3: norm + leaky + 64x64 GEMM via tf32 mma (split hi/lo)
// block = 128 edges x 64 outs, 8 warps: wm = wid&3 (M=32 each), wn = wid>>2 (N=32)
#define XSTR 68
__global__ void __launch_bounds__(256) k_stage(const float* __restrict__ W) {
    extern __shared__ float sm[];
    float* sX    = sm;                 // [128][68]
    float* sWm   = sm + 128*XSTR;      // [64][68]
    float* sStat = sm + 128*XSTR + 64*XSTR;  // [128]

    int tid = threadIdx.x;
    int b = blockIdx.x >> 11;
    size_t bb = (size_t)blockIdx.x * 128;   // first edge of block

    // W: row-major [o][c] -> sWm[o*68+c]
    #pragma unroll
    for (int i = tid; i < 4096; i += 256)
        sWm[(i >> 6)*XSTR + (i & 63)] = W[i];
    if (tid < 128) sStat[tid] = 0.f;

    // X: load, normalize, leaky, store to smem (stride 68)
    #pragma unroll
    for (int p = 0; p < 8; p++) {
        int c4 = p*2 + (tid >> 7);
        int eL = tid & 127;
        float4 v  = g_Y[(size_t)c4*NE + bb + eL];
        float4 sc = __ldg(&((const float4*)g_s)[b*16 + c4]);
        float4 tt = __ldg(&((const float4*)g_t)[b*16 + c4]);
        float4 x;
        x.x = fmaf(v.x, sc.x, tt.x); x.x = (x.x>=0.f)?x.x:SLOPE*x.x;
        x.y = fmaf(v.y, sc.y, tt.y); x.y = (x.y>=0.f)?x.y:SLOPE*x.y;
        x.z = fmaf(v.z, sc.z, tt.z); x.z = (x.z>=0.f)?x.z:SLOPE*x.z;
        x.w = fmaf(v.w, sc.w, tt.w); x.w = (x.w>=0.f)?x.w:SLOPE*x.w;
        *((float4*)&sX[eL*XSTR + c4*4]) = x;
    }
    __syncthreads();

    int lane = tid & 31, wid = tid >> 5;
    int gid = lane >> 2, tig = lane & 3;
    int m0 = (wid & 3) * 32, n0 = (wid >> 2) * 32;

    float acc[2][4][4];
    #pragma unroll
    for (int mt = 0; mt < 2; mt++)
        #pragma unroll
        for (int nt = 0; nt < 4; nt++)
            #pragma unroll
            for (int r = 0; r < 4; r++) acc[mt][nt][r] = 0.f;

    #pragma unroll
    for (int ks = 0; ks < 8; ks++) {
        int k0 = ks*8;
        unsigned ah[2][4], al[2][4];
        #pragma unroll
        for (int mt = 0; mt < 2; mt++) {
            const float* base = sX + (m0 + mt*16 + gid)*XSTR + k0 + tig;
            float x0 = base[0], x1 = base[8*XSTR], x2 = base[4], x3 = base[8*XSTR + 4];
            ah[mt][0] = tf32h(x0); al[mt][0] = tf32h(x0 - __uint_as_float(ah[mt][0]));
            ah[mt][1] = tf32h(x1); al[mt][1] = tf32h(x1 - __uint_as_float(ah[mt][1]));
            ah[mt][2] = tf32h(x2); al[mt][2] = tf32h(x2 - __uint_as_float(ah[mt][2]));
            ah[mt][3] = tf32h(x3); al[mt][3] = tf32h(x3 - __uint_as_float(ah[mt][3]));
        }
        unsigned bh[4][2], bl[4][2];
        #pragma unroll
        for (int nt = 0; nt < 4; nt++) {
            const float* base = sWm + (n0 + nt*8 + gid)*XSTR + k0 + tig;
            float w0 = base[0], w1 = base[4];
            bh[nt][0] = tf32h(w0); bl[nt][0] = tf32h(w0 - __uint_as_float(bh[nt][0]));
            bh[nt][1] = tf32h(w1); bl[nt][1] = tf32h(w1 - __uint_as_float(bh[nt][1]));
        }
        #pragma unroll
        for (int mt = 0; mt < 2; mt++)
            #pragma unroll
            for (int nt = 0; nt < 4; nt++) {
                mma8(acc[mt][nt], ah[mt][0],ah[mt][1],ah[mt][2],ah[mt][3], bh[nt][0],bh[nt][1]);
                mma8(acc[mt][nt], ah[mt][0],ah[mt][1],ah[mt][2],ah[mt][3], bl[nt][0],bl[nt][1]);
                mma8(acc[mt][nt], al[mt][0],al[mt][1],al[mt][2],al[mt][3], bh[nt][0],bh[nt][1]);
            }
    }

    // store results + fused stats
    #pragma unroll
    for (int mt = 0; mt < 2; mt++) {
        #pragma unroll
        for (int nt = 0; nt < 4; nt++) {
            int ch0 = n0 + nt*8 + 2*tig;
            int plane = ch0 >> 2, slot = tig & 1;
            size_t eg = bb + m0 + mt*16 + gid;
            float2* d0 = (float2*)&g_Y[(size_t)plane*NE + eg];
            d0[slot] = make_float2(acc[mt][nt][0], acc[mt][nt][1]);
            float2* d2 = (float2*)&g_Y[(size_t)plane*NE + eg + 8];
            d2[slot] = make_float2(acc[mt][nt][2], acc[mt][nt][3]);
        }
    }
    float s8[8], q8[8];
    #pragma unroll
    for (int nt = 0; nt < 4; nt++) {
        #pragma unroll
        for (int par = 0; par < 2; par++) {
            float a = acc[0][nt][par],   c = acc[0][nt][par+2];
            float d = acc[1][nt][par],   e = acc[1][nt][par+2];
            s8[nt*2+par] = (a + c) + (d + e);
            q8[nt*2+par] = fmaf(a,a, fmaf(c,c, fmaf(d,d, e*e)));
        }
    }
    #pragma unroll
    for (int off = 16; off >= 4; off >>= 1) {
        #pragma unroll
        for (int i = 0; i < 8; i++) {
            s8[i] += __shfl_down_sync(0xffffffffu, s8[i], off);
            q8[i] += __shfl_down_sync(0xffffffffu, q8[i], off);
        }
    }
    if (lane < 4) {   // gid == 0, lane = tig
        #pragma unroll
        for (int nt = 0; nt < 4; nt++) {
            #pragma unroll
            for (int par = 0; par < 2; par++) {
                int ch = n0 + nt*8 + 2*lane + par;
                atomicAdd(&sStat[ch], s8[nt*2+par]);
                atomicAdd(&sStat[64+ch], q8[nt*2+par]);
            }
        }
    }
    __syncthreads();
    if (tid < 128) {
        float v = sStat[tid];
        if (tid < 64) atomicAdd(&g_sum[b*64 + tid], v);
        else          atomicAdd(&g_sumsq[b*64 + tid - 64], v);
    }
}

// -------- final: norm3 + leaky + max over K (warp per (point, c4)), coalesced
__global__ void __launch_bounds__(256) k_out(float* __restrict__ out) {
    int w    = blockIdx.x * 8 + (threadIdx.x >> 5);   // warp id: (r, c4)
    int lane = threadIdx.x & 31;
    int c4 = w & 15;
    int r  = w >> 4;                 // b*N + n
    int b  = r >> 13;
    float4 sc = ((const float4*)g_s)[b*16 + c4];
    float4 tt = ((const float4*)g_t)[b*16 + c4];
    float4 v = g_Y[(size_t)c4*NE + (size_t)r*KNN + lane];
    float4 y;
    y.x = fmaf(v.x, sc.x, tt.x); y.x = (y.x>=0.f)?y.x:SLOPE*y.x;
    y.y = fmaf(v.y, sc.y, tt.y); y.y = (y.y>=0.f)?y.y:SLOPE*y.y;
    y.z = fmaf(v.z, sc.z, tt.z); y.z = (y.z>=0.f)?y.z:SLOPE*y.z;
    y.w = fmaf(v.w, sc.w, tt.w); y.w = (y.w>=0.f)?y.w:SLOPE*y.w;
    #pragma unroll
    for (int off = 16; off; off >>= 1) {
        y.x = fmaxf(y.x, __shfl_xor_sync(0xffffffffu, y.x, off));
        y.y = fmaxf(y.y, __shfl_xor_sync(0xffffffffu, y.y, off));
        y.z = fmaxf(y.z, __shfl_xor_sync(0xffffffffu, y.z, off));
        y.w = fmaxf(y.w, __shfl_xor_sync(0xffffffffu, y.w, off));
    }
    if (lane == 0) ((float4*)out)[(size_t)r*16 + c4] = y;
}

// ---------------------------------------------------------------------------
#define STAGE_SMEM ((128*XSTR + 64*XSTR + 128) * (int)sizeof(float))

extern "C" void kernel_launch(void* const* d_in, const int* in_sizes, int n_in,
                              void* d_out, int out_size)
{
    const float* signal = (const float*)d_in[0];
    const int*   edges  = (const int*)d_in[1];
    const float* efeat  = (const float*)d_in[2];
    // d_in[3] = k (constant 32, baked in)
    const float* W1 = (const float*)d_in[4];
    const float* g1 = (const float*)d_in[5];
    const float* b1 = (const float*)d_in[6];
    const float* W2 = (const float*)d_in[7];
    const float* g2 = (const float*)d_in[8];
    const float* b2 = (const float*)d_in[9];
    const float* W3 = (const float*)d_in[10];
    const float* g3 = (const float*)d_in[11];
    const float* b3 = (const float*)d_in[12];
    float* out = (float*)d_out;

    cudaFuncSetAttribute(k_stage, cudaFuncAttributeMaxDynamicSharedMemorySize, STAGE_SMEM);

    k_zero<<<1, 256>>>();
    k_stage1<<<NE/128, 256>>>(signal, edges, efeat, W1);
    k_finalize<<<1, 256>>>(g1, b1);
    k_stage<<<NE/128, 256, STAGE_SMEM>>>(W2);
    k_finalize<<<1, 256>>>(g2, b2);
    k_stage<<<NE/128, 256, STAGE_SMEM>>>(W3);
    k_finalize<<<1, 256>>>(g3, b3);
    k_out<<<(NB*NPTS*16)/8, 256>>>(out);
}

// round 7
// speedup vs baseline: 2.3291x; 1.1910x over previous
#include <cuda_runtime.h>
#include <math.h>

#define NB    4
#define NPTS  8192
#define KNN   32
#define NE    (NB*NPTS*KNN)      /* 1048576 edges */
#define EPB   (NPTS*KNN)         /* 262144 edges per batch */
#define BC    256
#define CNTF  ((float)EPB)
#define EPSV  1e-5f
#define SLOPE 0.1f

// SoA by channel-quad: plane c4 holds float4 of channels [4c4,4c4+4) per edge
__device__ float4 g_Y[(size_t)16 * NE];
__device__ __align__(16) float g_sum[BC], g_sumsq[BC], g_s[BC], g_t[BC];

// ---------------------------------------------------------------- helpers
__device__ __forceinline__ unsigned tf32h(float x) {
    unsigned r;
    asm("cvt.rna.tf32.f32 %0, %1;" : "=r"(r) : "f"(x));
    return r;
}
__device__ __forceinline__ void mma8(float* c,
                                     unsigned a0, unsigned a1, unsigned a2, unsigned a3,
                                     unsigned b0, unsigned b1) {
    asm("mma.sync.aligned.m16n8k8.row.col.f32.tf32.tf32.f32 "
        "{%0,%1,%2,%3},{%4,%5,%6,%7},{%8,%9},{%0,%1,%2,%3};"
        : "+f"(c[0]), "+f"(c[1]), "+f"(c[2]), "+f"(c[3])
        : "r"(a0), "r"(a1), "r"(a2), "r"(a3), "r"(b0), "r"(b1));
}

// ---------------------------------------------------------------- zero stats
__global__ void k_zero() {
    int i = threadIdx.x;
    g_sum[i] = 0.f; g_sumsq[i] = 0.f;
}

// ------ shared mma epilogue: store 128x64 tile to g_Y planes + fused stats
__device__ __forceinline__ void mma_epilogue(float acc[2][4][4], size_t bb, int b,
                                             float* sStat) {
    int tid = threadIdx.x;
    int lane = tid & 31, wid = tid >> 5;
    int gid = lane >> 2, tig = lane & 3;
    int m0 = (wid & 3) * 32, n0 = (wid >> 2) * 32;

    #pragma unroll
    for (int mt = 0; mt < 2; mt++) {
        #pragma unroll
        for (int nt = 0; nt < 4; nt++) {
            int ch0 = n0 + nt*8 + 2*tig;
            int plane = ch0 >> 2, slot = tig & 1;
            size_t eg = bb + m0 + mt*16 + gid;
            float2* d0 = (float2*)&g_Y[(size_t)plane*NE + eg];
            d0[slot] = make_float2(acc[mt][nt][0], acc[mt][nt][1]);
            float2* d2 = (float2*)&g_Y[(size_t)plane*NE + eg + 8];
            d2[slot] = make_float2(acc[mt][nt][2], acc[mt][nt][3]);
        }
    }
    float s8[8], q8[8];
    #pragma unroll
    for (int nt = 0; nt < 4; nt++) {
        #pragma unroll
        for (int par = 0; par < 2; par++) {
            float a = acc[0][nt][par],   c = acc[0][nt][par+2];
            float d = acc[1][nt][par],   e = acc[1][nt][par+2];
            s8[nt*2+par] = (a + c) + (d + e);
            q8[nt*2+par] = fmaf(a,a, fmaf(c,c, fmaf(d,d, e*e)));
        }
    }
    #pragma unroll
    for (int off = 16; off >= 4; off >>= 1) {
        #pragma unroll
        for (int i = 0; i < 8; i++) {
            s8[i] += __shfl_down_sync(0xffffffffu, s8[i], off);
            q8[i] += __shfl_down_sync(0xffffffffu, q8[i], off);
        }
    }
    if (lane < 4) {   // gid == 0, lane = tig
        #pragma unroll
        for (int nt = 0; nt < 4; nt++) {
            #pragma unroll
            for (int par = 0; par < 2; par++) {
                int ch = n0 + nt*8 + 2*lane + par;
                atomicAdd(&sStat[ch], s8[nt*2+par]);
                atomicAdd(&sStat[64+ch], q8[nt*2+par]);
            }
        }
    }
    __syncthreads();
    if (tid < 128) {
        float v = sStat[tid];
        if (tid < 64) atomicAdd(&g_sum[b*64 + tid], v);
        else          atomicAdd(&g_sumsq[b*64 + tid - 64], v);
    }
}

// ------- stage 1: gather + concat + GEMM1 via tf32 mma (K padded 35->40)
#define X1STR 44
__global__ void __launch_bounds__(256) k_stage1(
    const float* __restrict__ signal, const int* __restrict__ edges,
    const float* __restrict__ efeat,  const float* __restrict__ W1)
{
    __shared__ __align__(16) float sX[128*X1STR];
    __shared__ __align__(16) float sWm[64*X1STR];
    __shared__ float sStat[128];

    int tid = threadIdx.x;
    int b = blockIdx.x >> 11;                  // 2048 blocks per batch
    size_t bb = (size_t)blockIdx.x * 128;

    // W1: row-major [o][c], c<35 -> sWm[o*44+c]; pad c=35..39 with 0
    for (int i = tid; i < 64*35; i += 256) {
        int o = i / 35, c = i - o*35;
        sWm[o*X1STR + c] = W1[i];
    }
    for (int i = tid; i < 64*5; i += 256) {
        int o = i / 5, c = 35 + (i - o*5);
        sWm[o*X1STR + c] = 0.f;
    }
    for (int i = tid; i < 128*5; i += 256) {
        int e = i / 5, c = 35 + (i - e*5);
        sX[e*X1STR + c] = 0.f;
    }
    if (tid < 128) sStat[tid] = 0.f;

    // gather: 2 threads per edge, 16 floats each (signal row = 32 floats)
    {
        int eL = tid >> 1, part = tid & 1;
        int idx = edges[bb + eL];
        const float4* src = (const float4*)signal + (size_t)idx*8 + part*4;
        float4* dst = (float4*)&sX[eL*X1STR + part*16];
        dst[0]=src[0]; dst[1]=src[1]; dst[2]=src[2]; dst[3]=src[3];
    }
    if (tid < 128) {
        size_t base = 3*(bb + tid);
        sX[tid*X1STR+32] = efeat[base];
        sX[tid*X1STR+33] = efeat[base+1];
        sX[tid*X1STR+34] = efeat[base+2];
    }
    __syncthreads();

    int lane = tid & 31, wid = tid >> 5;
    int gid = lane >> 2, tig = lane & 3;
    int m0 = (wid & 3) * 32, n0 = (wid >> 2) * 32;

    float acc[2][4][4];
    #pragma unroll
    for (int mt = 0; mt < 2; mt++)
        #pragma unroll
        for (int nt = 0; nt < 4; nt++)
            #pragma unroll
            for (int r = 0; r < 4; r++) acc[mt][nt][r] = 0.f;

    #pragma unroll
    for (int ks = 0; ks < 5; ks++) {
        int k0 = ks*8;
        unsigned ah[2][4], al[2][4];
        #pragma unroll
        for (int mt = 0; mt < 2; mt++) {
            const float* base = sX + (m0 + mt*16 + gid)*X1STR + k0 + tig;
            float x0 = base[0], x1 = base[8*X1STR], x2 = base[4], x3 = base[8*X1STR + 4];
            ah[mt][0] = tf32h(x0); al[mt][0] = tf32h(x0 - __uint_as_float(ah[mt][0]));
            ah[mt][1] = tf32h(x1); al[mt][1] = tf32h(x1 - __uint_as_float(ah[mt][1]));
            ah[mt][2] = tf32h(x2); al[mt][2] = tf32h(x2 - __uint_as_float(ah[mt][2]));
            ah[mt][3] = tf32h(x3); al[mt][3] = tf32h(x3 - __uint_as_float(ah[mt][3]));
        }
        unsigned bh[4][2], bl[4][2];
        #pragma unroll
        for (int nt = 0; nt < 4; nt++) {
            const float* base = sWm + (n0 + nt*8 + gid)*X1STR + k0 + tig;
            float w0 = base[0], w1 = base[4];
            bh[nt][0] = tf32h(w0); bl[nt][0] = tf32h(w0 - __uint_as_float(bh[nt][0]));
            bh[nt][1] = tf32h(w1); bl[nt][1] = tf32h(w1 - __uint_as_float(bh[nt][1]));
        }
        #pragma unroll
        for (int mt = 0; mt < 2; mt++)
            #pragma unroll
            for (int nt = 0; nt < 4; nt++) {
                mma8(acc[mt][nt], ah[mt][0],ah[mt][1],ah[mt][2],ah[mt][3], bh[nt][0],bh[nt][1]);
                mma8(acc[mt][nt], ah[mt][0],ah[mt][1],ah[mt][2],ah[mt][3], bl[nt][0],bl[nt][1]);
                mma8(acc[mt][nt], al[mt][0],al[mt][1],al[mt][2],al[mt][3], bh[nt][0],bh[nt][1]);
            }
    }
    mma_epilogue(acc, bb, b, sStat);
}

// ------------------------------------- stats -> (scale, shift), reset accum
__global__ void k_finalize(const float* __restrict__ gam, const float* __restrict__ bet) {
    int i = threadIdx.x;          // 256 = (b,c)
    float mean = g_sum[i]   * (1.f/CNTF);
    float var  = g_sumsq[i] * (1.f/CNTF) - mean*mean;
    float sc   = gam[i & 63] * rsqrtf(var + EPSV);
    g_s[i] = sc;
    g_t[i] = bet[i & 63] - mean * sc;
    g_sum[i] = 0.f; g_sumsq[i] = 0.f;
}

// ------- stages 2/3: norm + leaky + 64x64 GEMM via tf32 mma (split hi/lo)
#define XSTR 68
__global__ void __launch_bounds__(256) k_stage(const float* __restrict__ W) {
    extern __shared__ float sm[];
    float* sX    = sm;                 // [128][68]
    float* sWm   = sm + 128*XSTR;      // [64][68]
    float* sStat = sm + 128*XSTR + 64*XSTR;  // [128]

    int tid = threadIdx.x;
    int b = blockIdx.x >> 11;
    size_t bb = (size_t)blockIdx.x * 128;   // first edge of block

    #pragma unroll
    for (int i = tid; i < 4096; i += 256)
        sWm[(i >> 6)*XSTR + (i & 63)] = W[i];
    if (tid < 128) sStat[tid] = 0.f;

    // X: load, normalize, leaky, store to smem (stride 68)
    #pragma unroll
    for (int p = 0; p < 8; p++) {
        int c4 = p*2 + (tid >> 7);
        int eL = tid & 127;
        float4 v  = g_Y[(size_t)c4*NE + bb + eL];
        float4 sc = __ldg(&((const float4*)g_s)[b*16 + c4]);
        float4 tt = __ldg(&((const float4*)g_t)[b*16 + c4]);
        float4 x;
        x.x = fmaf(v.x, sc.x, tt.x); x.x = (x.x>=0.f)?x.x:SLOPE*x.x;
        x.y = fmaf(v.y, sc.y, tt.y); x.y = (x.y>=0.f)?x.y:SLOPE*x.y;
        x.z = fmaf(v.z, sc.z, tt.z); x.z = (x.z>=0.f)?x.z:SLOPE*x.z;
        x.w = fmaf(v.w, sc.w, tt.w); x.w = (x.w>=0.f)?x.w:SLOPE*x.w;
        *((float4*)&sX[eL*XSTR + c4*4]) = x;
    }
    __syncthreads();

    int lane = tid & 31, wid = tid >> 5;
    int gid = lane >> 2, tig = lane & 3;
    int m0 = (wid & 3) * 32, n0 = (wid >> 2) * 32;

    float acc[2][4][4];
    #pragma unroll
    for (int mt = 0; mt < 2; mt++)
        #pragma unroll
        for (int nt = 0; nt < 4; nt++)
            #pragma unroll
            for (int r = 0; r < 4; r++) acc[mt][nt][r] = 0.f;

    #pragma unroll
    for (int ks = 0; ks < 8; ks++) {
        int k0 = ks*8;
        unsigned ah[2][4], al[2][4];
        #pragma unroll
        for (int mt = 0; mt < 2; mt++) {
            const float* base = sX + (m0 + mt*16 + gid)*XSTR + k0 + tig;
            float x0 = base[0], x1 = base[8*XSTR], x2 = base[4], x3 = base[8*XSTR + 4];
            ah[mt][0] = tf32h(x0); al[mt][0] = tf32h(x0 - __uint_as_float(ah[mt][0]));
            ah[mt][1] = tf32h(x1); al[mt][1] = tf32h(x1 - __uint_as_float(ah[mt][1]));
            ah[mt][2] = tf32h(x2); al[mt][2] = tf32h(x2 - __uint_as_float(ah[mt][2]));
            ah[mt][3] = tf32h(x3); al[mt][3] = tf32h(x3 - __uint_as_float(ah[mt][3]));
        }
        unsigned bh[4][2], bl[4][2];
        #pragma unroll
        for (int nt = 0; nt < 4; nt++) {
            const float* base = sWm + (n0 + nt*8 + gid)*XSTR + k0 + tig;
            float w0 = base[0], w1 = base[4];
            bh[nt][0] = tf32h(w0); bl[nt][0] = tf32h(w0 - __uint_as_float(bh[nt][0]));
            bh[nt][1] = tf32h(w1); bl[nt][1] = tf32h(w1 - __uint_as_float(bh[nt][1]));
        }
        #pragma unroll
        for (int mt = 0; mt < 2; mt++)
            #pragma unroll
            for (int nt = 0; nt < 4; nt++) {
                mma8(acc[mt][nt], ah[mt][0],ah[mt][1],ah[mt][2],ah[mt][3], bh[nt][0],bh[nt][1]);
                mma8(acc[mt][nt], ah[mt][0],ah[mt][1],ah[mt][2],ah[mt][3], bl[nt][0],bl[nt][1]);
                mma8(acc[mt][nt], al[mt][0],al[mt][1],al[mt][2],al[mt][3], bh[nt][0],bh[nt][1]);
            }
    }
    mma_epilogue(acc, bb, b, sStat);
}

// -------- final: norm3 + leaky + max over K (warp per (point, c4)), coalesced
__global__ void __launch_bounds__(256) k_out(float* __restrict__ out) {
    int w    = blockIdx.x * 8 + (threadIdx.x >> 5);   // warp id: (r, c4)
    int lane = threadIdx.x & 31;
    int c4 = w & 15;
    int r  = w >> 4;                 // b*N + n
    int b  = r >> 13;
    float4 sc = ((const float4*)g_s)[b*16 + c4];
    float4 tt = ((const float4*)g_t)[b*16 + c4];
    float4 v = g_Y[(size_t)c4*NE + (size_t)r*KNN + lane];
    float4 y;
    y.x = fmaf(v.x, sc.x, tt.x); y.x = (y.x>=0.f)?y.x:SLOPE*y.x;
    y.y = fmaf(v.y, sc.y, tt.y); y.y = (y.y>=0.f)?y.y:SLOPE*y.y;
    y.z = fmaf(v.z, sc.z, tt.z); y.z = (y.z>=0.f)?y.z:SLOPE*y.z;
    y.w = fmaf(v.w, sc.w, tt.w); y.w = (y.w>=0.f)?y.w:SLOPE*y.w;
    #pragma unroll
    for (int off = 16; off; off >>= 1) {
        y.x = fmaxf(y.x, __shfl_xor_sync(0xffffffffu, y.x, off));
        y.y = fmaxf(y.y, __shfl_xor_sync(0xffffffffu, y.y, off));
        y.z = fmaxf(y.z, __shfl_xor_sync(0xffffffffu, y.z, off));
        y.w = fmaxf(y.w, __shfl_xor_sync(0xffffffffu, y.w, off));
    }
    if (lane == 0) ((float4*)out)[(size_t)r*16 + c4] = y;
}

// ---------------------------------------------------------------------------
#define STAGE_SMEM ((128*XSTR + 64*XSTR + 128) * (int)sizeof(float))

extern "C" void kernel_launch(void* const* d_in, const int* in_sizes, int n_in,
                              void* d_out, int out_size)
{
    const float* signal = (const float*)d_in[0];
    const int*   edges  = (const int*)d_in[1];
    const float* efeat  = (const float*)d_in[2];
    // d_in[3] = k (constant 32, baked in)
    const float* W1 = (const float*)d_in[4];
    const float* g1 = (const float*)d_in[5];
    const float* b1 = (const float*)d_in[6];
    const float* W2 = (const float*)d_in[7];
    const float* g2 = (const float*)d_in[8];
    const float* b2 = (const float*)d_in[9];
    const float* W3 = (const float*)d_in[10];
    const float* g3 = (const float*)d_in[11];
    const float* b3 = (const float*)d_in[12];
    float* out = (float*)d_out;

    cudaFuncSetAttribute(k_stage, cudaFuncAttributeMaxDynamicSharedMemorySize, STAGE_SMEM);

    k_zero<<<1, 256>>>();
    k_stage1<<<NE/128, 256>>>(signal, edges, efeat, W1);
    k_finalize<<<1, 256>>>(g1, b1);
    k_stage<<<NE/128, 256, STAGE_SMEM>>>(W2);
    k_finalize<<<1, 256>>>(g2, b2);
    k_stage<<<NE/128, 256, STAGE_SMEM>>>(W3);
    k_finalize<<<1, 256>>>(g3, b3);
    k_out<<<(NB*NPTS*16)/8, 256>>>(out);
}

// round 8
// speedup vs baseline: 2.6461x; 1.1361x over previous
#include <cuda_runtime.h>
#include <math.h>

#define NB    4
#define NPTS  8192
#define KNN   32
#define NE    (NB*NPTS*KNN)      /* 1048576 edges */
#define EPB   (NPTS*KNN)         /* 262144 edges per batch */
#define BC    256
#define CNTF  ((float)EPB)
#define EPSV  1e-5f
#define SLOPE 0.1f

// SoA by channel-quad: plane c4 holds float4 of channels [4c4,4c4+4) per edge
__device__ float4 g_Y[(size_t)16 * NE];
__device__ __align__(16) float g_sum[BC], g_sumsq[BC], g_s[BC], g_t[BC];

// ---------------------------------------------------------------- helpers
// split two floats into packed bf16x2 hi + bf16x2 lo (element0 in low half)
__device__ __forceinline__ uint2 split2(float x0, float x1) {
    unsigned h, l;
    asm("cvt.rn.bf16x2.f32 %0, %1, %2;" : "=r"(h) : "f"(x1), "f"(x0));
    float h0 = __uint_as_float(h << 16);
    float h1 = __uint_as_float(h & 0xffff0000u);
    asm("cvt.rn.bf16x2.f32 %0, %1, %2;" : "=r"(l) : "f"(x1 - h1), "f"(x0 - h0));
    return make_uint2(h, l);
}
__device__ __forceinline__ void mma16(float* c,
                                      unsigned a0, unsigned a1, unsigned a2, unsigned a3,
                                      unsigned b0, unsigned b1) {
    asm("mma.sync.aligned.m16n8k16.row.col.f32.bf16.bf16.f32 "
        "{%0,%1,%2,%3},{%4,%5,%6,%7},{%8,%9},{%0,%1,%2,%3};"
        : "+f"(c[0]), "+f"(c[1]), "+f"(c[2]), "+f"(c[3])
        : "r"(a0), "r"(a1), "r"(a2), "r"(a3), "r"(b0), "r"(b1));
}

// ---------------------------------------------------------------- zero stats
__global__ void k_zero() {
    int i = threadIdx.x;
    g_sum[i] = 0.f; g_sumsq[i] = 0.f;
}

// ------ shared mma epilogue: store 128x64 tile to g_Y planes + fused stats
__device__ __forceinline__ void mma_epilogue(float acc[2][4][4], size_t bb, int b,
                                             float* sStat) {
    int tid = threadIdx.x;
    int lane = tid & 31, wid = tid >> 5;
    int gid = lane >> 2, tig = lane & 3;
    int m0 = (wid & 3) * 32, n0 = (wid >> 2) * 32;

    #pragma unroll
    for (int mt = 0; mt < 2; mt++) {
        #pragma unroll
        for (int nt = 0; nt < 4; nt++) {
            int ch0 = n0 + nt*8 + 2*tig;
            int plane = ch0 >> 2, slot = tig & 1;
            size_t eg = bb + m0 + mt*16 + gid;
            float2* d0 = (float2*)&g_Y[(size_t)plane*NE + eg];
            d0[slot] = make_float2(acc[mt][nt][0], acc[mt][nt][1]);
            float2* d2 = (float2*)&g_Y[(size_t)plane*NE + eg + 8];
            d2[slot] = make_float2(acc[mt][nt][2], acc[mt][nt][3]);
        }
    }
    float s8[8], q8[8];
    #pragma unroll
    for (int nt = 0; nt < 4; nt++) {
        #pragma unroll
        for (int par = 0; par < 2; par++) {
            float a = acc[0][nt][par],   c = acc[0][nt][par+2];
            float d = acc[1][nt][par],   e = acc[1][nt][par+2];
            s8[nt*2+par] = (a + c) + (d + e);
            q8[nt*2+par] = fmaf(a,a, fmaf(c,c, fmaf(d,d, e*e)));
        }
    }
    #pragma unroll
    for (int off = 16; off >= 4; off >>= 1) {
        #pragma unroll
        for (int i = 0; i < 8; i++) {
            s8[i] += __shfl_down_sync(0xffffffffu, s8[i], off);
            q8[i] += __shfl_down_sync(0xffffffffu, q8[i], off);
        }
    }
    if (lane < 4) {
        #pragma unroll
        for (int nt = 0; nt < 4; nt++) {
            #pragma unroll
            for (int par = 0; par < 2; par++) {
                int ch = n0 + nt*8 + 2*lane + par;
                atomicAdd(&sStat[ch], s8[nt*2+par]);
                atomicAdd(&sStat[64+ch], q8[nt*2+par]);
            }
        }
    }
    __syncthreads();
    if (tid < 128) {
        float v = sStat[tid];
        if (tid < 64) atomicAdd(&g_sum[b*64 + tid], v);
        else          atomicAdd(&g_sumsq[b*64 + tid - 64], v);
    }
}

// smem layout (both GEMM kernels), stride 36 words (36 mod 32 == 4 -> no bank conflicts)
#define PSTR 36
#define OFF_XH 0
#define OFF_XL (128*PSTR)
#define OFF_WH (256*PSTR)
#define OFF_WL (256*PSTR + 64*PSTR)
#define OFF_ST (256*PSTR + 128*PSTR)
#define STAGE_SMEM ((384*PSTR + 128) * (int)sizeof(unsigned))

// ---------------- common bf16 mma mainloop over NCHUNK k16-chunks ----------
template<int NCHUNK>
__device__ __forceinline__ void mma_main(const unsigned* sm, float acc[2][4][4]) {
    int tid = threadIdx.x;
    int lane = tid & 31, wid = tid >> 5;
    int gid = lane >> 2, tig = lane & 3;
    int m0 = (wid & 3) * 32, n0 = (wid >> 2) * 32;

    #pragma unroll
    for (int mt = 0; mt < 2; mt++)
        #pragma unroll
        for (int nt = 0; nt < 4; nt++)
            #pragma unroll
            for (int r = 0; r < 4; r++) acc[mt][nt][r] = 0.f;

    #pragma unroll
    for (int ks = 0; ks < NCHUNK; ks++) {
        int col = ks*8 + tig;
        unsigned ah[2][4], al[2][4];
        #pragma unroll
        for (int mt = 0; mt < 2; mt++) {
            int r0 = (m0 + mt*16 + gid)*PSTR, r1 = r0 + 8*PSTR;
            ah[mt][0] = sm[OFF_XH + r0 + col];     al[mt][0] = sm[OFF_XL + r0 + col];
            ah[mt][1] = sm[OFF_XH + r1 + col];     al[mt][1] = sm[OFF_XL + r1 + col];
            ah[mt][2] = sm[OFF_XH + r0 + col + 4]; al[mt][2] = sm[OFF_XL + r0 + col + 4];
            ah[mt][3] = sm[OFF_XH + r1 + col + 4]; al[mt][3] = sm[OFF_XL + r1 + col + 4];
        }
        unsigned bh[4][2], bl[4][2];
        #pragma unroll
        for (int nt = 0; nt < 4; nt++) {
            int rn = (n0 + nt*8 + gid)*PSTR;
            bh[nt][0] = sm[OFF_WH + rn + col];     bl[nt][0] = sm[OFF_WL + rn + col];
            bh[nt][1] = sm[OFF_WH + rn + col + 4]; bl[nt][1] = sm[OFF_WL + rn + col + 4];
        }
        #pragma unroll
        for (int mt = 0; mt < 2; mt++)
            #pragma unroll
            for (int nt = 0; nt < 4; nt++) {
                mma16(acc[mt][nt], ah[mt][0],ah[mt][1],ah[mt][2],ah[mt][3], bh[nt][0],bh[nt][1]);
                mma16(acc[mt][nt], ah[mt][0],ah[mt][1],ah[mt][2],ah[mt][3], bl[nt][0],bl[nt][1]);
                mma16(acc[mt][nt], al[mt][0],al[mt][1],al[mt][2],al[mt][3], bh[nt][0],bh[nt][1]);
            }
    }
}

// ------- stage 1: gather + concat + GEMM1 (K=35 padded to 48, 3 chunks)
__global__ void __launch_bounds__(256) k_stage1(
    const float* __restrict__ signal, const int* __restrict__ edges,
    const float* __restrict__ efeat,  const float* __restrict__ W1)
{
    extern __shared__ unsigned sm[];
    float* sStat = (float*)(sm + OFF_ST);

    int tid = threadIdx.x;
    int b = blockIdx.x >> 11;
    size_t bb = (size_t)blockIdx.x * 128;

    // zero pad columns: X pairs 17..23, W pairs 17..23  (cols = pair index)
    for (int i = tid; i < 128*7; i += 256) {
        int e = i / 7, cp = 17 + (i - (i/7)*7);
        sm[OFF_XH + e*PSTR + cp] = 0u; sm[OFF_XL + e*PSTR + cp] = 0u;
    }
    for (int i = tid; i < 64*7; i += 256) {
        int o = i / 7, cp = 17 + (i - (i/7)*7);
        sm[OFF_WH + o*PSTR + cp] = 0u; sm[OFF_WL + o*PSTR + cp] = 0u;
    }
    // W1 [64][35] -> pairs 0..16 + pair 17 = (c34, 0)
    for (int p = tid; p < 64*17; p += 256) {
        int o = p / 17, cp = p - (p/17)*17;
        float w0 = W1[o*35 + 2*cp];
        float w1 = (cp < 17) ? ((2*cp+1 < 35) ? W1[o*35 + 2*cp + 1] : 0.f) : 0.f;
        uint2 hl = split2(w0, w1);
        sm[OFF_WH + o*PSTR + cp] = hl.x; sm[OFF_WL + o*PSTR + cp] = hl.y;
    }
    if (tid < 64) {  // pair 17: (c34, 0)
        uint2 hl = split2(W1[tid*35 + 34], 0.f);
        sm[OFF_WH + tid*PSTR + 17] = hl.x; sm[OFF_WL + tid*PSTR + 17] = hl.y;
    }
    if (tid < 128) sStat[tid] = 0.f;

    // gather: 2 threads per edge, 16 floats each -> pairs part*8 .. part*8+7
    {
        int eL = tid >> 1, part = tid & 1;
        int idx = edges[bb + eL];
        const float4* src = (const float4*)signal + (size_t)idx*8 + part*4;
        #pragma unroll
        for (int q = 0; q < 4; q++) {
            float4 v = src[q];
            uint2 h0 = split2(v.x, v.y);
            uint2 h1 = split2(v.z, v.w);
            int cp = part*8 + q*2;
            sm[OFF_XH + eL*PSTR + cp]     = h0.x; sm[OFF_XL + eL*PSTR + cp]     = h0.y;
            sm[OFF_XH + eL*PSTR + cp + 1] = h1.x; sm[OFF_XL + eL*PSTR + cp + 1] = h1.y;
        }
    }
    if (tid < 128) {  // edge feats: pair 16 = (c32,c33), pair 17 = (c34, 0)
        size_t base = 3*(bb + tid);
        float f0 = efeat[base], f1 = efeat[base+1], f2 = efeat[base+2];
        uint2 h0 = split2(f0, f1);
        uint2 h1 = split2(f2, 0.f);
        sm[OFF_XH + tid*PSTR + 16] = h0.x; sm[OFF_XL + tid*PSTR + 16] = h0.y;
        sm[OFF_XH + tid*PSTR + 17] = h1.x; sm[OFF_XL + tid*PSTR + 17] = h1.y;
    }
    __syncthreads();

    float acc[2][4][4];
    mma_main<3>(sm, acc);
    mma_epilogue(acc, bb, b, sStat);
}

// ------------------------------------- stats -> (scale, shift), reset accum
__global__ void k_finalize(const float* __restrict__ gam, const float* __restrict__ bet) {
    int i = threadIdx.x;
    float mean = g_sum[i]   * (1.f/CNTF);
    float var  = g_sumsq[i] * (1.f/CNTF) - mean*mean;
    float sc   = gam[i & 63] * rsqrtf(var + EPSV);
    g_s[i] = sc;
    g_t[i] = bet[i & 63] - mean * sc;
    g_sum[i] = 0.f; g_sumsq[i] = 0.f;
}

// ------- stages 2/3: norm + leaky + 64x64 GEMM (K=64, 4 chunks)
__global__ void __launch_bounds__(256) k_stage(const float* __restrict__ W) {
    extern __shared__ unsigned sm[];
    float* sStat = (float*)(sm + OFF_ST);

    int tid = threadIdx.x;
    int b = blockIdx.x >> 11;
    size_t bb = (size_t)blockIdx.x * 128;

    // W [64][64] -> 2048 pairs
    #pragma unroll
    for (int p = tid; p < 2048; p += 256) {
        int o = p >> 5, cp = p & 31;
        float2 w = *(const float2*)&W[o*64 + 2*cp];
        uint2 hl = split2(w.x, w.y);
        sm[OFF_WH + o*PSTR + cp] = hl.x; sm[OFF_WL + o*PSTR + cp] = hl.y;
    }
    if (tid < 128) sStat[tid] = 0.f;

    // X: load plane quads, normalize + leaky, split, store pairs
    #pragma unroll
    for (int p = 0; p < 8; p++) {
        int c4 = p*2 + (tid >> 7);
        int eL = tid & 127;
        float4 v  = g_Y[(size_t)c4*NE + bb + eL];
        float4 sc = __ldg(&((const float4*)g_s)[b*16 + c4]);
        float4 tt = __ldg(&((const float4*)g_t)[b*16 + c4]);
        float4 x;
        x.x = fmaf(v.x, sc.x, tt.x); x.x = (x.x>=0.f)?x.x:SLOPE*x.x;
        x.y = fmaf(v.y, sc.y, tt.y); x.y = (x.y>=0.f)?x.y:SLOPE*x.y;
        x.z = fmaf(v.z, sc.z, tt.z); x.z = (x.z>=0.f)?x.z:SLOPE*x.z;
        x.w = fmaf(v.w, sc.w, tt.w); x.w = (x.w>=0.f)?x.w:SLOPE*x.w;
        uint2 h0 = split2(x.x, x.y);
        uint2 h1 = split2(x.z, x.w);
        sm[OFF_XH + eL*PSTR + 2*c4]     = h0.x; sm[OFF_XL + eL*PSTR + 2*c4]     = h0.y;
        sm[OFF_XH + eL*PSTR + 2*c4 + 1] = h1.x; sm[OFF_XL + eL*PSTR + 2*c4 + 1] = h1.y;
    }
    __syncthreads();

    float acc[2][4][4];
    mma_main<4>(sm, acc);
    mma_epilogue(acc, bb, b, sStat);
}

// -------- final: norm3 + leaky + max over K (warp per (point, c4)), coalesced
__global__ void __launch_bounds__(256) k_out(float* __restrict__ out) {
    int w    = blockIdx.x * 8 + (threadIdx.x >> 5);
    int lane = threadIdx.x & 31;
    int c4 = w & 15;
    int r  = w >> 4;
    int b  = r >> 13;
    float4 sc = ((const float4*)g_s)[b*16 + c4];
    float4 tt = ((const float4*)g_t)[b*16 + c4];
    float4 v = g_Y[(size_t)c4*NE + (size_t)r*KNN + lane];
    float4 y;
    y.x = fmaf(v.x, sc.x, tt.x); y.x = (y.x>=0.f)?y.x:SLOPE*y.x;
    y.y = fmaf(v.y, sc.y, tt.y); y.y = (y.y>=0.f)?y.y:SLOPE*y.y;
    y.z = fmaf(v.z, sc.z, tt.z); y.z = (y.z>=0.f)?y.z:SLOPE*y.z;
    y.w = fmaf(v.w, sc.w, tt.w); y.w = (y.w>=0.f)?y.w:SLOPE*y.w;
    #pragma unroll
    for (int off = 16; off; off >>= 1) {
        y.x = fmaxf(y.x, __shfl_xor_sync(0xffffffffu, y.x, off));
        y.y = fmaxf(y.y, __shfl_xor_sync(0xffffffffu, y.y, off));
        y.z = fmaxf(y.z, __shfl_xor_sync(0xffffffffu, y.z, off));
        y.w = fmaxf(y.w, __shfl_xor_sync(0xffffffffu, y.w, off));
    }
    if (lane == 0) ((float4*)out)[(size_t)r*16 + c4] = y;
}

// ---------------------------------------------------------------------------
extern "C" void kernel_launch(void* const* d_in, const int* in_sizes, int n_in,
                              void* d_out, int out_size)
{
    const float* signal = (const float*)d_in[0];
    const int*   edges  = (const int*)d_in[1];
    const float* efeat  = (const float*)d_in[2];
    // d_in[3] = k (constant 32, baked in)
    const float* W1 = (const float*)d_in[4];
    const float* g1 = (const float*)d_in[5];
    const float* b1 = (const float*)d_in[6];
    const float* W2 = (const float*)d_in[7];
    const float* g2 = (const float*)d_in[8];
    const float* b2 = (const float*)d_in[9];
    const float* W3 = (const float*)d_in[10];
    const float* g3 = (const float*)d_in[11];
    const float* b3 = (const float*)d_in[12];
    float* out = (float*)d_out;

    cudaFuncSetAttribute(k_stage1, cudaFuncAttributeMaxDynamicSharedMemorySize, STAGE_SMEM);
    cudaFuncSetAttribute(k_stage,  cudaFuncAttributeMaxDynamicSharedMemorySize, STAGE_SMEM);

    k_zero<<<1, 256>>>();
    k_stage1<<<NE/128, 256, STAGE_SMEM>>>(signal, edges, efeat, W1);
    k_finalize<<<1, 256>>>(g1, b1);
    k_stage<<<NE/128, 256, STAGE_SMEM>>>(W2);
    k_finalize<<<1, 256>>>(g2, b2);
    k_stage<<<NE/128, 256, STAGE_SMEM>>>(W3);
    k_finalize<<<1, 256>>>(g3, b3);
    k_out<<<(NB*NPTS*16)/8, 256>>>(out);
}

// round 9
// speedup vs baseline: 2.6533x; 1.0027x over previous
#include <cuda_runtime.h>
#include <math.h>

#define NB    4
#define NPTS  8192
#define KNN   32
#define NE    (NB*NPTS*KNN)      /* 1048576 edges */
#define EPB   (NPTS*KNN)         /* 262144 edges per batch */
#define BC    256
#define CNTF  ((float)EPB)
#define EPSV  1e-5f
#define SLOPE 0.1f

// SoA by channel-quad: plane c4 holds float4 of channels [4c4,4c4+4) per edge
__device__ float4 g_Y[(size_t)16 * NE];
__device__ __align__(16) float g_sum[BC], g_sumsq[BC], g_s[BC], g_t[BC];

// ---------------------------------------------------------------- helpers
// split two floats into packed bf16x2 hi + bf16x2 lo (element0 in low half)
__device__ __forceinline__ uint2 split2(float x0, float x1) {
    unsigned h, l;
    asm("cvt.rn.bf16x2.f32 %0, %1, %2;" : "=r"(h) : "f"(x1), "f"(x0));
    float h0 = __uint_as_float(h << 16);
    float h1 = __uint_as_float(h & 0xffff0000u);
    asm("cvt.rn.bf16x2.f32 %0, %1, %2;" : "=r"(l) : "f"(x1 - h1), "f"(x0 - h0));
    return make_uint2(h, l);
}
__device__ __forceinline__ void mma16(float* c,
                                      unsigned a0, unsigned a1, unsigned a2, unsigned a3,
                                      unsigned b0, unsigned b1) {
    asm("mma.sync.aligned.m16n8k16.row.col.f32.bf16.bf16.f32 "
        "{%0,%1,%2,%3},{%4,%5,%6,%7},{%8,%9},{%0,%1,%2,%3};"
        : "+f"(c[0]), "+f"(c[1]), "+f"(c[2]), "+f"(c[3])
        : "r"(a0), "r"(a1), "r"(a2), "r"(a3), "r"(b0), "r"(b1));
}
__device__ __forceinline__ void ldsm4(unsigned& r0, unsigned& r1,
                                      unsigned& r2, unsigned& r3, unsigned a) {
    asm volatile("ldmatrix.sync.aligned.m8n8.x4.shared.b16 {%0,%1,%2,%3}, [%4];"
        : "=r"(r0), "=r"(r1), "=r"(r2), "=r"(r3) : "r"(a));
}
__device__ __forceinline__ unsigned s2u(const void* p) {
    return (unsigned)__cvta_generic_to_shared(p);
}

// ---------------------------------------------------------------- zero stats
__global__ void k_zero() {
    int i = threadIdx.x;
    g_sum[i] = 0.f; g_sumsq[i] = 0.f;
}

// ------ shared mma epilogue: store 128x64 tile to g_Y planes + fused stats
__device__ __forceinline__ void mma_epilogue(float acc[2][4][4], size_t bb, int b,
                                             float* sStat) {
    int tid = threadIdx.x;
    int lane = tid & 31, wid = tid >> 5;
    int gid = lane >> 2, tig = lane & 3;
    int m0 = (wid & 3) * 32, n0 = (wid >> 2) * 32;

    #pragma unroll
    for (int mt = 0; mt < 2; mt++) {
        #pragma unroll
        for (int nt = 0; nt < 4; nt++) {
            int ch0 = n0 + nt*8 + 2*tig;
            int plane = ch0 >> 2, slot = tig & 1;
            size_t eg = bb + m0 + mt*16 + gid;
            float2* d0 = (float2*)&g_Y[(size_t)plane*NE + eg];
            d0[slot] = make_float2(acc[mt][nt][0], acc[mt][nt][1]);
            float2* d2 = (float2*)&g_Y[(size_t)plane*NE + eg + 8];
            d2[slot] = make_float2(acc[mt][nt][2], acc[mt][nt][3]);
        }
    }
    float s8[8], q8[8];
    #pragma unroll
    for (int nt = 0; nt < 4; nt++) {
        #pragma unroll
        for (int par = 0; par < 2; par++) {
            float a = acc[0][nt][par],   c = acc[0][nt][par+2];
            float d = acc[1][nt][par],   e = acc[1][nt][par+2];
            s8[nt*2+par] = (a + c) + (d + e);
            q8[nt*2+par] = fmaf(a,a, fmaf(c,c, fmaf(d,d, e*e)));
        }
    }
    #pragma unroll
    for (int off = 16; off >= 4; off >>= 1) {
        #pragma unroll
        for (int i = 0; i < 8; i++) {
            s8[i] += __shfl_down_sync(0xffffffffu, s8[i], off);
            q8[i] += __shfl_down_sync(0xffffffffu, q8[i], off);
        }
    }
    if (lane < 4) {
        #pragma unroll
        for (int nt = 0; nt < 4; nt++) {
            #pragma unroll
            for (int par = 0; par < 2; par++) {
                int ch = n0 + nt*8 + 2*lane + par;
                atomicAdd(&sStat[ch], s8[nt*2+par]);
                atomicAdd(&sStat[64+ch], q8[nt*2+par]);
            }
        }
    }
    __syncthreads();
    if (tid < 128) {
        float v = sStat[tid];
        if (tid < 64) atomicAdd(&g_sum[b*64 + tid], v);
        else          atomicAdd(&g_sumsq[b*64 + tid - 64], v);
    }
}

// smem layout, stride 36 words (36 mod 32 == 4 -> conflict-free; 144B rows, 16B aligned)
#define PSTR 36
#define OFF_XH 0
#define OFF_XL (128*PSTR)
#define OFF_WH (256*PSTR)
#define OFF_WL (256*PSTR + 64*PSTR)
#define OFF_ST (256*PSTR + 128*PSTR)
#define STAGE_SMEM ((384*PSTR + 128) * (int)sizeof(unsigned))

// ---------------- common bf16 mma mainloop (LDSM fragment loads) ----------
template<int NCHUNK>
__device__ __forceinline__ void mma_main(const unsigned* sm, float acc[2][4][4]) {
    int tid = threadIdx.x;
    int lane = tid & 31, wid = tid >> 5;
    int m0 = (wid & 3) * 32, n0 = (wid >> 2) * 32;
    int g = lane >> 3, lr = lane & 7;

    // A addrs: lane-group g -> (row += (g&1)*8, col += (g>>1)*4)
    int arow = m0 + lr + (g & 1)*8;
    int acol = (g >> 1)*4;
    unsigned aH0 = s2u(sm + OFF_XH + arow*PSTR + acol);
    unsigned aH1 = aH0 + 16*PSTR*4;
    unsigned aL0 = aH0 + (OFF_XL - OFF_XH)*4;
    unsigned aL1 = aH1 + (OFF_XL - OFF_XH)*4;
    // B addrs: lane-group g -> (row += (g>>1)*8, col += (g&1)*4); nt pair via +16 rows
    int brow = n0 + lr + (g >> 1)*8;
    int bcol = (g & 1)*4;
    unsigned bH0 = s2u(sm + OFF_WH + brow*PSTR + bcol);
    unsigned bH1 = bH0 + 16*PSTR*4;
    unsigned bL0 = bH0 + 64*PSTR*4;
    unsigned bL1 = bH1 + 64*PSTR*4;

    #pragma unroll
    for (int mt = 0; mt < 2; mt++)
        #pragma unroll
        for (int nt = 0; nt < 4; nt++)
            #pragma unroll
            for (int r = 0; r < 4; r++) acc[mt][nt][r] = 0.f;

    #pragma unroll
    for (int ks = 0; ks < NCHUNK; ks++) {
        unsigned off = ks*32;   // 8 words per chunk
        unsigned ah[2][4], al[2][4], bh[4][2], bl[4][2];
        ldsm4(ah[0][0], ah[0][1], ah[0][2], ah[0][3], aH0 + off);
        ldsm4(ah[1][0], ah[1][1], ah[1][2], ah[1][3], aH1 + off);
        ldsm4(al[0][0], al[0][1], al[0][2], al[0][3], aL0 + off);
        ldsm4(al[1][0], al[1][1], al[1][2], al[1][3], aL1 + off);
        ldsm4(bh[0][0], bh[0][1], bh[1][0], bh[1][1], bH0 + off);
        ldsm4(bh[2][0], bh[2][1], bh[3][0], bh[3][1], bH1 + off);
        ldsm4(bl[0][0], bl[0][1], bl[1][0], bl[1][1], bL0 + off);
        ldsm4(bl[2][0], bl[2][1], bl[3][0], bl[3][1], bL1 + off);
        #pragma unroll
        for (int mt = 0; mt < 2; mt++)
            #pragma unroll
            for (int nt = 0; nt < 4; nt++) {
                mma16(acc[mt][nt], ah[mt][0],ah[mt][1],ah[mt][2],ah[mt][3], bh[nt][0],bh[nt][1]);
                mma16(acc[mt][nt], ah[mt][0],ah[mt][1],ah[mt][2],ah[mt][3], bl[nt][0],bl[nt][1]);
                mma16(acc[mt][nt], al[mt][0],al[mt][1],al[mt][2],al[mt][3], bh[nt][0],bh[nt][1]);
            }
    }
}

// ------- stage 1: gather + concat + GEMM1 (K=35 padded to 48, 3 chunks)
__global__ void __launch_bounds__(256) k_stage1(
    const float* __restrict__ signal, const int* __restrict__ edges,
    const float* __restrict__ efeat,  const float* __restrict__ W1)
{
    extern __shared__ unsigned sm[];
    float* sStat = (float*)(sm + OFF_ST);

    int tid = threadIdx.x;
    int b = blockIdx.x >> 11;
    size_t bb = (size_t)blockIdx.x * 128;

    // zero pad columns: X pairs 17..23, W pairs 17..23
    for (int i = tid; i < 128*7; i += 256) {
        int e = i / 7, cp = 17 + (i - (i/7)*7);
        sm[OFF_XH + e*PSTR + cp] = 0u; sm[OFF_XL + e*PSTR + cp] = 0u;
    }
    for (int i = tid; i < 64*7; i += 256) {
        int o = i / 7, cp = 17 + (i - (i/7)*7);
        sm[OFF_WH + o*PSTR + cp] = 0u; sm[OFF_WL + o*PSTR + cp] = 0u;
    }
    // W1 [64][35] -> pairs 0..16 + pair 17 = (c34, 0)
    for (int p = tid; p < 64*17; p += 256) {
        int o = p / 17, cp = p - (p/17)*17;
        float w0 = W1[o*35 + 2*cp];
        float w1 = (2*cp+1 < 35) ? W1[o*35 + 2*cp + 1] : 0.f;
        uint2 hl = split2(w0, w1);
        sm[OFF_WH + o*PSTR + cp] = hl.x; sm[OFF_WL + o*PSTR + cp] = hl.y;
    }
    if (tid < 64) {
        uint2 hl = split2(W1[tid*35 + 34], 0.f);
        sm[OFF_WH + tid*PSTR + 17] = hl.x; sm[OFF_WL + tid*PSTR + 17] = hl.y;
    }
    if (tid < 128) sStat[tid] = 0.f;

    // gather: 2 threads per edge, 16 floats each -> pairs part*8 .. part*8+7
    {
        int eL = tid >> 1, part = tid & 1;
        int idx = edges[bb + eL];
        const float4* src = (const float4*)signal + (size_t)idx*8 + part*4;
        #pragma unroll
        for (int q = 0; q < 4; q++) {
            float4 v = src[q];
            uint2 h0 = split2(v.x, v.y);
            uint2 h1 = split2(v.z, v.w);
            int cp = part*8 + q*2;
            sm[OFF_XH + eL*PSTR + cp]     = h0.x; sm[OFF_XL + eL*PSTR + cp]     = h0.y;
            sm[OFF_XH + eL*PSTR + cp + 1] = h1.x; sm[OFF_XL + eL*PSTR + cp + 1] = h1.y;
        }
    }
    if (tid < 128) {  // edge feats: pair 16 = (c32,c33), pair 17 = (c34, 0)
        size_t base = 3*(bb + tid);
        float f0 = efeat[base], f1 = efeat[base+1], f2 = efeat[base+2];
        uint2 h0 = split2(f0, f1);
        uint2 h1 = split2(f2, 0.f);
        sm[OFF_XH + tid*PSTR + 16] = h0.x; sm[OFF_XL + tid*PSTR + 16] = h0.y;
        sm[OFF_XH + tid*PSTR + 17] = h1.x; sm[OFF_XL + tid*PSTR + 17] = h1.y;
    }
    __syncthreads();

    float acc[2][4][4];
    mma_main<3>(sm, acc);
    mma_epilogue(acc, bb, b, sStat);
}

// ------------------------------------- stats -> (scale, shift), reset accum
__global__ void k_finalize(const float* __restrict__ gam, const float* __restrict__ bet) {
    int i = threadIdx.x;
    float mean = g_sum[i]   * (1.f/CNTF);
    float var  = g_sumsq[i] * (1.f/CNTF) - mean*mean;
    float sc   = gam[i & 63] * rsqrtf(var + EPSV);
    g_s[i] = sc;
    g_t[i] = bet[i & 63] - mean * sc;
    g_sum[i] = 0.f; g_sumsq[i] = 0.f;
}

// ------- stages 2/3: norm + leaky + 64x64 GEMM (K=64, 4 chunks)
__global__ void __launch_bounds__(256) k_stage(const float* __restrict__ W) {
    extern __shared__ unsigned sm[];
    float* sStat = (float*)(sm + OFF_ST);

    int tid = threadIdx.x;
    int b = blockIdx.x >> 11;
    size_t bb = (size_t)blockIdx.x * 128;

    // W [64][64] -> 2048 pairs
    #pragma unroll
    for (int p = tid; p < 2048; p += 256) {
        int o = p >> 5, cp = p & 31;
        float2 w = *(const float2*)&W[o*64 + 2*cp];
        uint2 hl = split2(w.x, w.y);
        sm[OFF_WH + o*PSTR + cp] = hl.x; sm[OFF_WL + o*PSTR + cp] = hl.y;
    }
    if (tid < 128) sStat[tid] = 0.f;

    // X: load plane quads, normalize + leaky, split, store pairs
    #pragma unroll
    for (int p = 0; p < 8; p++) {
        int c4 = p*2 + (tid >> 7);
        int eL = tid & 127;
        float4 v  = g_Y[(size_t)c4*NE + bb + eL];
        float4 sc = __ldg(&((const float4*)g_s)[b*16 + c4]);
        float4 tt = __ldg(&((const float4*)g_t)[b*16 + c4]);
        float4 x;
        x.x = fmaf(v.x, sc.x, tt.x); x.x = (x.x>=0.f)?x.x:SLOPE*x.x;
        x.y = fmaf(v.y, sc.y, tt.y); x.y = (x.y>=0.f)?x.y:SLOPE*x.y;
        x.z = fmaf(v.z, sc.z, tt.z); x.z = (x.z>=0.f)?x.z:SLOPE*x.z;
        x.w = fmaf(v.w, sc.w, tt.w); x.w = (x.w>=0.f)?x.w:SLOPE*x.w;
        uint2 h0 = split2(x.x, x.y);
        uint2 h1 = split2(x.z, x.w);
        sm[OFF_XH + eL*PSTR + 2*c4]     = h0.x; sm[OFF_XL + eL*PSTR + 2*c4]     = h0.y;
        sm[OFF_XH + eL*PSTR + 2*c4 + 1] = h1.x; sm[OFF_XL + eL*PSTR + 2*c4 + 1] = h1.y;
    }
    __syncthreads();

    float acc[2][4][4];
    mma_main<4>(sm, acc);
    mma_epilogue(acc, bb, b, sStat);
}

// -------- final: norm3 + leaky + max over K (warp per (point, c4)), coalesced
__global__ void __launch_bounds__(256) k_out(float* __restrict__ out) {
    int w    = blockIdx.x * 8 + (threadIdx.x >> 5);
    int lane = threadIdx.x & 31;
    int c4 = w & 15;
    int r  = w >> 4;
    int b  = r >> 13;
    float4 sc = ((const float4*)g_s)[b*16 + c4];
    float4 tt = ((const float4*)g_t)[b*16 + c4];
    float4 v = g_Y[(size_t)c4*NE + (size_t)r*KNN + lane];
    float4 y;
    y.x = fmaf(v.x, sc.x, tt.x); y.x = (y.x>=0.f)?y.x:SLOPE*y.x;
    y.y = fmaf(v.y, sc.y, tt.y); y.y = (y.y>=0.f)?y.y:SLOPE*y.y;
    y.z = fmaf(v.z, sc.z, tt.z); y.z = (y.z>=0.f)?y.z:SLOPE*y.z;
    y.w = fmaf(v.w, sc.w, tt.w); y.w = (y.w>=0.f)?y.w:SLOPE*y.w;
    #pragma unroll
    for (int off = 16; off; off >>= 1) {
        y.x = fmaxf(y.x, __shfl_xor_sync(0xffffffffu, y.x, off));
        y.y = fmaxf(y.y, __shfl_xor_sync(0xffffffffu, y.y, off));
        y.z = fmaxf(y.z, __shfl_xor_sync(0xffffffffu, y.z, off));
        y.w = fmaxf(y.w, __shfl_xor_sync(0xffffffffu, y.w, off));
    }
    if (lane == 0) ((float4*)out)[(size_t)r*16 + c4] = y;
}

// ---------------------------------------------------------------------------
extern "C" void kernel_launch(void* const* d_in, const int* in_sizes, int n_in,
                              void* d_out, int out_size)
{
    const float* signal = (const float*)d_in[0];
    const int*   edges  = (const int*)d_in[1];
    const float* efeat  = (const float*)d_in[2];
    // d_in[3] = k (constant 32, baked in)
    const float* W1 = (const float*)d_in[4];
    const float* g1 = (const float*)d_in[5];
    const float* b1 = (const float*)d_in[6];
    const float* W2 = (const float*)d_in[7];
    const float* g2 = (const float*)d_in[8];
    const float* b2 = (const float*)d_in[9];
    const float* W3 = (const float*)d_in[10];
    const float* g3 = (const float*)d_in[11];
    const float* b3 = (const float*)d_in[12];
    float* out = (float*)d_out;

    cudaFuncSetAttribute(k_stage1, cudaFuncAttributeMaxDynamicSharedMemorySize, STAGE_SMEM);
    cudaFuncSetAttribute(k_stage,  cudaFuncAttributeMaxDynamicSharedMemorySize, STAGE_SMEM);

    k_zero<<<1, 256>>>();
    k_stage1<<<NE/128, 256, STAGE_SMEM>>>(signal, edges, efeat, W1);
    k_finalize<<<1, 256>>>(g1, b1);
    k_stage<<<NE/128, 256, STAGE_SMEM>>>(W2);
    k_finalize<<<1, 256>>>(g2, b2);
    k_stage<<<NE/128, 256, STAGE_SMEM>>>(W3);
    k_finalize<<<1, 256>>>(g3, b3);
    k_out<<<(NB*NPTS*16)/8, 256>>>(out);
}